// round 4
// baseline (speedup 1.0000x reference)
#include <cuda_runtime.h>
#include <cuda_bf16.h>
#include <cstdint>

namespace {

constexpr int L  = 2048;   // sequence length
constexpr int CH = 64;     // head dim
constexpr int BT = 64;     // query tile per CTA
constexpr int BS = 64;     // key/value tile per iteration
constexpr int QS = 68;     // sQ row stride (floats), layout [t][c] (overlaid on sP)
constexpr int KS = 72;     // sK row stride, layout [c][s]
constexpr int VS = 68;     // sV row stride, layout [c][s]
constexpr int PS = 68;     // sP row stride, layout [t][s]
constexpr int NTHREADS = 128;

constexpr int OFF_P = 0;                 // sP / sQ overlay: [64][68]
constexpr int OFF_K = OFF_P + BT * PS;   // [64][72]
constexpr int OFF_V = OFF_K + CH * KS;   // [64][68]
constexpr int OFF_A = OFF_V + CH * VS;   // alpha[64]
constexpr int OFF_L = OFF_A + BT;        // 1/l  [64]
constexpr int SMEM_FLOATS = OFF_L + BT;
constexpr int SMEM_BYTES  = SMEM_FLOATS * 4;   // 53,760 B -> 4 CTAs/SM

__device__ __forceinline__ float tf32r(float x) {
    uint32_t u;
    asm("cvt.rna.tf32.f32 %0, %1;" : "=r"(u) : "f"(x));
    return __uint_as_float(u);
}
__device__ __forceinline__ uint32_t fb(float x) { return __float_as_uint(x); }

// D(16x8) += A(16x8,row) * B(8x8,col), tf32 inputs, f32 accumulate
__device__ __forceinline__ void mma8(float c[4], const uint32_t a[4],
                                     uint32_t b0, uint32_t b1) {
    asm volatile(
        "mma.sync.aligned.m16n8k8.row.col.f32.tf32.tf32.f32 "
        "{%0,%1,%2,%3}, {%4,%5,%6,%7}, {%8,%9}, {%0,%1,%2,%3};"
        : "+f"(c[0]), "+f"(c[1]), "+f"(c[2]), "+f"(c[3])
        : "r"(a[0]), "r"(a[1]), "r"(a[2]), "r"(a[3]), "r"(b0), "r"(b1));
}

__global__ void __launch_bounds__(NTHREADS, 4)
attn_kernel(const float* __restrict__ qkv, float* __restrict__ out)
{
    extern __shared__ float sm[];
    float* sP  = sm + OFF_P;   // [BT][PS]  t x s   (P tile; also sQ [t][c] during prologue)
    float* sK  = sm + OFF_K;   // [CH][KS]  c x s
    float* sV  = sm + OFF_V;   // [CH][VS]  c x s
    float* sA  = sm + OFF_A;   // alpha per t-row
    float* sLi = sm + OFF_L;   // 1/l per t-row
    float* sQ  = sP;           // overlay

    const int tid  = threadIdx.x;
    const int lane = tid & 31;
    const int wid  = tid >> 5;
    const int g4   = lane >> 2;   // groupID (0..7)
    const int q4   = lane & 3;    // thread-in-group

    const int t0   = blockIdx.x * BT;
    const int head = blockIdx.y;          // 0..31  == b*8 + h
    const int b    = head >> 3;
    const int h    = head & 7;

    const float* gQ = qkv + (size_t)(b * 1536 +        h * 64) * L;
    const float* gK = qkv + (size_t)(b * 1536 +  512 + h * 64) * L;
    const float* gV = qkv + (size_t)(b * 1536 + 1024 + h * 64) * L;
    float*       gO = out + (size_t)(b * 512  +        h * 64) * L;

    const int tr = wid * 16 + g4;   // local t-row (GEMM1 / softmax)
    const int cr = wid * 16 + g4;   // local c-row (GEMM2 / output)

    // ---- prologue: stage Q transposed sQ[t][c] (scaled by 1/8, tf32), hoist A-fragments
    {
        const int r0 = tid >> 4;            // channel row
        const int c4 = (tid & 15) << 2;     // t offset
        #pragma unroll
        for (int r = r0; r < CH; r += 8) {
            float4 v = *(const float4*)(gQ + (size_t)r * L + t0 + c4);
            sQ[(c4 + 0) * QS + r] = tf32r(v.x * 0.125f);
            sQ[(c4 + 1) * QS + r] = tf32r(v.y * 0.125f);
            sQ[(c4 + 2) * QS + r] = tf32r(v.z * 0.125f);
            sQ[(c4 + 3) * QS + r] = tf32r(v.w * 0.125f);
        }
    }
    __syncthreads();

    uint32_t aq[8][4];
    #pragma unroll
    for (int k = 0; k < 8; k++) {
        const int kc = k * 8 + q4;
        aq[k][0] = fb(sQ[ tr      * QS + kc    ]);
        aq[k][1] = fb(sQ[(tr + 8) * QS + kc    ]);
        aq[k][2] = fb(sQ[ tr      * QS + kc + 4]);
        aq[k][3] = fb(sQ[(tr + 8) * QS + kc + 4]);
    }
    __syncthreads();   // all warps done reading sQ before sP overwrites it

    // Output accumulators: O^T tile, warp owns channel rows [16*wid,+16), all 64 t-cols
    float oc[8][4];
    #pragma unroll
    for (int n = 0; n < 8; n++) {
        oc[n][0] = 0.f; oc[n][1] = 0.f; oc[n][2] = 0.f; oc[n][3] = 0.f;
    }
    float m0 = -INFINITY, m1 = -INFINITY, l0 = 0.f, l1 = 0.f;

    for (int sb = 0; sb < L; sb += BS) {
        // ---- stage K, V tiles: tf32-round in registers, STS.128 (conflict-free)
        {
            const int r0 = tid >> 4;
            const int c4 = (tid & 15) << 2;
            #pragma unroll
            for (int r = r0; r < CH; r += 8) {
                float4 kv = *(const float4*)(gK + (size_t)r * L + sb + c4);
                float4 kr = make_float4(tf32r(kv.x), tf32r(kv.y), tf32r(kv.z), tf32r(kv.w));
                *(float4*)(sK + r * KS + c4) = kr;
                float4 vv = *(const float4*)(gV + (size_t)r * L + sb + c4);
                float4 vr = make_float4(tf32r(vv.x), tf32r(vv.y), tf32r(vv.z), tf32r(vv.w));
                *(float4*)(sV + r * VS + c4) = vr;
            }
        }
        __syncthreads();

        // ---- GEMM1: S(t x s) = Qt(t x c) * K(c x s); warp's 16 t-rows x 64 s-cols
        float sc[8][4];
        #pragma unroll
        for (int n = 0; n < 8; n++) {
            sc[n][0] = 0.f; sc[n][1] = 0.f; sc[n][2] = 0.f; sc[n][3] = 0.f;
        }
        #pragma unroll
        for (int n = 0; n < 8; n++) {
            const int bn = n * 8 + g4;
            #pragma unroll
            for (int k = 0; k < 8; k++) {
                const int br = k * 8 + q4;
                uint32_t b0 = fb(sK[ br      * KS + bn]);
                uint32_t b1 = fb(sK[(br + 4) * KS + bn]);
                mma8(sc[n], aq[k], b0, b1);
            }
        }

        // ---- online softmax over this s-block (rows tr, tr+8)
        float mx0 = -INFINITY, mx1 = -INFINITY;
        #pragma unroll
        for (int n = 0; n < 8; n++) {
            mx0 = fmaxf(mx0, fmaxf(sc[n][0], sc[n][1]));
            mx1 = fmaxf(mx1, fmaxf(sc[n][2], sc[n][3]));
        }
        mx0 = fmaxf(mx0, __shfl_xor_sync(0xFFFFFFFFu, mx0, 1));
        mx0 = fmaxf(mx0, __shfl_xor_sync(0xFFFFFFFFu, mx0, 2));
        mx1 = fmaxf(mx1, __shfl_xor_sync(0xFFFFFFFFu, mx1, 1));
        mx1 = fmaxf(mx1, __shfl_xor_sync(0xFFFFFFFFu, mx1, 2));

        const float mn0 = fmaxf(m0, mx0);
        const float mn1 = fmaxf(m1, mx1);
        const float al0 = __expf(m0 - mn0);
        const float al1 = __expf(m1 - mn1);

        float s0 = 0.f, s1 = 0.f;
        #pragma unroll
        for (int n = 0; n < 8; n++) {
            sc[n][0] = __expf(sc[n][0] - mn0);
            sc[n][1] = __expf(sc[n][1] - mn0);
            sc[n][2] = __expf(sc[n][2] - mn1);
            sc[n][3] = __expf(sc[n][3] - mn1);
            s0 += sc[n][0] + sc[n][1];
            s1 += sc[n][2] + sc[n][3];
        }
        s0 += __shfl_xor_sync(0xFFFFFFFFu, s0, 1);
        s0 += __shfl_xor_sync(0xFFFFFFFFu, s0, 2);
        s1 += __shfl_xor_sync(0xFFFFFFFFu, s1, 1);
        s1 += __shfl_xor_sync(0xFFFFFFFFu, s1, 2);

        l0 = l0 * al0 + s0;  m0 = mn0;
        l1 = l1 * al1 + s1;  m1 = mn1;

        // ---- store P natural [t][s] with float2 stores; publish alpha per t-row
        #pragma unroll
        for (int n = 0; n < 8; n++) {
            const int scol = n * 8 + 2 * q4;
            *(float2*)(sP +  tr      * PS + scol) =
                make_float2(tf32r(sc[n][0]), tf32r(sc[n][1]));
            *(float2*)(sP + (tr + 8) * PS + scol) =
                make_float2(tf32r(sc[n][2]), tf32r(sc[n][3]));
        }
        if (q4 == 0) { sA[tr] = al0; sA[tr + 8] = al1; }
        __syncthreads();

        // ---- rescale O^T cols by alpha[t], then GEMM2: O^T(c x t) += V(c x s) * P^T(s x t)
        #pragma unroll
        for (int n = 0; n < 8; n++) {
            const float av0 = sA[n * 8 + 2 * q4];
            const float av1 = sA[n * 8 + 2 * q4 + 1];
            oc[n][0] *= av0; oc[n][1] *= av1;
            oc[n][2] *= av0; oc[n][3] *= av1;
        }
        uint32_t av[8][4];
        #pragma unroll
        for (int k = 0; k < 8; k++) {
            const int kk = k * 8 + q4;
            av[k][0] = fb(sV[ cr      * VS + kk    ]);
            av[k][1] = fb(sV[(cr + 8) * VS + kk    ]);
            av[k][2] = fb(sV[ cr      * VS + kk + 4]);
            av[k][3] = fb(sV[(cr + 8) * VS + kk + 4]);
        }
        #pragma unroll
        for (int n = 0; n < 8; n++) {
            const int bn = n * 8 + g4;    // t-col group
            #pragma unroll
            for (int k = 0; k < 8; k++) {
                const int br = k * 8 + q4; // s-row
                uint32_t b0 = fb(sP[bn * PS + br    ]);
                uint32_t b1 = fb(sP[bn * PS + br + 4]);
                mma8(oc[n], av[k], b0, b1);
            }
        }
        __syncthreads();   // protect sK/sV/sP/sA before next iteration overwrites
    }

    // ---- finalize: divide columns by l[t], write O^T directly ([c][t] matches global)
    if (q4 == 0) { sLi[tr] = 1.0f / l0; sLi[tr + 8] = 1.0f / l1; }
    __syncthreads();

    #pragma unroll
    for (int n = 0; n < 8; n++) {
        const int tcol = n * 8 + 2 * q4;
        const float li0 = sLi[tcol];
        const float li1 = sLi[tcol + 1];
        float2 w0 = make_float2(oc[n][0] * li0, oc[n][1] * li1);
        float2 w1 = make_float2(oc[n][2] * li0, oc[n][3] * li1);
        *(float2*)(gO + (size_t)cr       * L + t0 + tcol) = w0;
        *(float2*)(gO + (size_t)(cr + 8) * L + t0 + tcol) = w1;
    }
}

} // anonymous namespace

extern "C" void kernel_launch(void* const* d_in, const int* in_sizes, int n_in,
                              void* d_out, int out_size)
{
    const float* qkv = (const float*)d_in[0];
    float* out = (float*)d_out;

    cudaFuncSetAttribute(attn_kernel,
                         cudaFuncAttributeMaxDynamicSharedMemorySize, SMEM_BYTES);

    dim3 grid(L / BT, 32);   // 32 t-tiles x 32 (batch*head)
    attn_kernel<<<grid, NTHREADS, SMEM_BYTES>>>(qkv, out);
}

// round 5
// speedup vs baseline: 1.0007x; 1.0007x over previous
#include <cuda_runtime.h>
#include <cuda_bf16.h>
#include <cstdint>

namespace {

constexpr int L  = 2048;   // sequence length
constexpr int CH = 64;     // head dim
constexpr int BT = 64;     // query tile per CTA
constexpr int BS = 64;     // key/value tile per iteration
constexpr int QS = 68;     // sQ row stride (floats), layout [t][c] (overlaid on sP)
constexpr int KS = 72;     // sK row stride, layout [c][s]
constexpr int VS = 68;     // sV row stride, layout [c][s]
constexpr int PS = 68;     // sP row stride, layout [t][s]
constexpr int NTHREADS = 128;

constexpr int OFF_P = 0;                 // sP / sQ overlay: [64][68]
constexpr int OFF_K = OFF_P + BT * PS;   // [64][72]
constexpr int OFF_V = OFF_K + CH * KS;   // [64][68]
constexpr int OFF_A = OFF_V + CH * VS;   // alpha[64]
constexpr int OFF_L = OFF_A + BT;        // 1/l  [64]
constexpr int SMEM_FLOATS = OFF_L + BT;
constexpr int SMEM_BYTES  = SMEM_FLOATS * 4;   // 53,760 B -> 4 CTAs/SM

__device__ __forceinline__ float tf32r(float x) {
    uint32_t u;
    asm("cvt.rna.tf32.f32 %0, %1;" : "=r"(u) : "f"(x));
    return __uint_as_float(u);
}
__device__ __forceinline__ uint32_t fb(float x) { return __float_as_uint(x); }

// D(16x8) += A(16x8,row) * B(8x8,col), tf32 inputs, f32 accumulate
__device__ __forceinline__ void mma8(float c[4], const uint32_t a[4],
                                     uint32_t b0, uint32_t b1) {
    asm volatile(
        "mma.sync.aligned.m16n8k8.row.col.f32.tf32.tf32.f32 "
        "{%0,%1,%2,%3}, {%4,%5,%6,%7}, {%8,%9}, {%0,%1,%2,%3};"
        : "+f"(c[0]), "+f"(c[1]), "+f"(c[2]), "+f"(c[3])
        : "r"(a[0]), "r"(a[1]), "r"(a[2]), "r"(a[3]), "r"(b0), "r"(b1));
}

__global__ void __launch_bounds__(NTHREADS, 4)
attn_kernel(const float* __restrict__ qkv, float* __restrict__ out)
{
    extern __shared__ float sm[];
    float* sP  = sm + OFF_P;   // [BT][PS]  t x s   (P tile; also sQ [t][c] during prologue)
    float* sK  = sm + OFF_K;   // [CH][KS]  c x s
    float* sV  = sm + OFF_V;   // [CH][VS]  c x s
    float* sA  = sm + OFF_A;   // alpha per t-row
    float* sLi = sm + OFF_L;   // 1/l per t-row
    float* sQ  = sP;           // overlay

    const int tid  = threadIdx.x;
    const int lane = tid & 31;
    const int wid  = tid >> 5;
    const int g4   = lane >> 2;   // groupID (0..7)
    const int q4   = lane & 3;    // thread-in-group

    const int t0   = blockIdx.x * BT;
    const int head = blockIdx.y;          // 0..31  == b*8 + h
    const int b    = head >> 3;
    const int h    = head & 7;

    const float* gQ = qkv + (size_t)(b * 1536 +        h * 64) * L;
    const float* gK = qkv + (size_t)(b * 1536 +  512 + h * 64) * L;
    const float* gV = qkv + (size_t)(b * 1536 + 1024 + h * 64) * L;
    float*       gO = out + (size_t)(b * 512  +        h * 64) * L;

    const int tr = wid * 16 + g4;   // local t-row (GEMM1 / softmax)
    const int cr = wid * 16 + g4;   // local c-row (GEMM2 / output)

    // ---- prologue: stage Q transposed sQ[t][c] (scaled by 1/8, tf32), hoist A-fragments
    {
        const int r0 = tid >> 4;            // channel row
        const int c4 = (tid & 15) << 2;     // t offset
        #pragma unroll
        for (int r = r0; r < CH; r += 8) {
            float4 v = *(const float4*)(gQ + (size_t)r * L + t0 + c4);
            sQ[(c4 + 0) * QS + r] = tf32r(v.x * 0.125f);
            sQ[(c4 + 1) * QS + r] = tf32r(v.y * 0.125f);
            sQ[(c4 + 2) * QS + r] = tf32r(v.z * 0.125f);
            sQ[(c4 + 3) * QS + r] = tf32r(v.w * 0.125f);
        }
    }
    __syncthreads();

    uint32_t aq[8][4];
    #pragma unroll
    for (int k = 0; k < 8; k++) {
        const int kc = k * 8 + q4;
        aq[k][0] = fb(sQ[ tr      * QS + kc    ]);
        aq[k][1] = fb(sQ[(tr + 8) * QS + kc    ]);
        aq[k][2] = fb(sQ[ tr      * QS + kc + 4]);
        aq[k][3] = fb(sQ[(tr + 8) * QS + kc + 4]);
    }
    __syncthreads();   // all warps done reading sQ before sP overwrites it

    // Output accumulators: O^T tile, warp owns channel rows [16*wid,+16), all 64 t-cols
    float oc[8][4];
    #pragma unroll
    for (int n = 0; n < 8; n++) {
        oc[n][0] = 0.f; oc[n][1] = 0.f; oc[n][2] = 0.f; oc[n][3] = 0.f;
    }
    float m0 = -INFINITY, m1 = -INFINITY, l0 = 0.f, l1 = 0.f;

    for (int sb = 0; sb < L; sb += BS) {
        // ---- stage K, V tiles: tf32-round in registers, STS.128 (conflict-free)
        {
            const int r0 = tid >> 4;
            const int c4 = (tid & 15) << 2;
            #pragma unroll
            for (int r = r0; r < CH; r += 8) {
                float4 kv = *(const float4*)(gK + (size_t)r * L + sb + c4);
                float4 kr = make_float4(tf32r(kv.x), tf32r(kv.y), tf32r(kv.z), tf32r(kv.w));
                *(float4*)(sK + r * KS + c4) = kr;
                float4 vv = *(const float4*)(gV + (size_t)r * L + sb + c4);
                float4 vr = make_float4(tf32r(vv.x), tf32r(vv.y), tf32r(vv.z), tf32r(vv.w));
                *(float4*)(sV + r * VS + c4) = vr;
            }
        }
        __syncthreads();

        // ---- GEMM1: S(t x s) = Qt(t x c) * K(c x s); warp's 16 t-rows x 64 s-cols
        float sc[8][4];
        #pragma unroll
        for (int n = 0; n < 8; n++) {
            sc[n][0] = 0.f; sc[n][1] = 0.f; sc[n][2] = 0.f; sc[n][3] = 0.f;
        }
        #pragma unroll
        for (int n = 0; n < 8; n++) {
            const int bn = n * 8 + g4;
            #pragma unroll
            for (int k = 0; k < 8; k++) {
                const int br = k * 8 + q4;
                uint32_t b0 = fb(sK[ br      * KS + bn]);
                uint32_t b1 = fb(sK[(br + 4) * KS + bn]);
                mma8(sc[n], aq[k], b0, b1);
            }
        }

        // ---- online softmax over this s-block (rows tr, tr+8)
        float mx0 = -INFINITY, mx1 = -INFINITY;
        #pragma unroll
        for (int n = 0; n < 8; n++) {
            mx0 = fmaxf(mx0, fmaxf(sc[n][0], sc[n][1]));
            mx1 = fmaxf(mx1, fmaxf(sc[n][2], sc[n][3]));
        }
        mx0 = fmaxf(mx0, __shfl_xor_sync(0xFFFFFFFFu, mx0, 1));
        mx0 = fmaxf(mx0, __shfl_xor_sync(0xFFFFFFFFu, mx0, 2));
        mx1 = fmaxf(mx1, __shfl_xor_sync(0xFFFFFFFFu, mx1, 1));
        mx1 = fmaxf(mx1, __shfl_xor_sync(0xFFFFFFFFu, mx1, 2));

        const float mn0 = fmaxf(m0, mx0);
        const float mn1 = fmaxf(m1, mx1);
        const float al0 = __expf(m0 - mn0);
        const float al1 = __expf(m1 - mn1);

        float s0 = 0.f, s1 = 0.f;
        #pragma unroll
        for (int n = 0; n < 8; n++) {
            sc[n][0] = __expf(sc[n][0] - mn0);
            sc[n][1] = __expf(sc[n][1] - mn0);
            sc[n][2] = __expf(sc[n][2] - mn1);
            sc[n][3] = __expf(sc[n][3] - mn1);
            s0 += sc[n][0] + sc[n][1];
            s1 += sc[n][2] + sc[n][3];
        }
        s0 += __shfl_xor_sync(0xFFFFFFFFu, s0, 1);
        s0 += __shfl_xor_sync(0xFFFFFFFFu, s0, 2);
        s1 += __shfl_xor_sync(0xFFFFFFFFu, s1, 1);
        s1 += __shfl_xor_sync(0xFFFFFFFFu, s1, 2);

        l0 = l0 * al0 + s0;  m0 = mn0;
        l1 = l1 * al1 + s1;  m1 = mn1;

        // ---- store P natural [t][s] with float2 stores; publish alpha per t-row
        #pragma unroll
        for (int n = 0; n < 8; n++) {
            const int scol = n * 8 + 2 * q4;
            *(float2*)(sP +  tr      * PS + scol) =
                make_float2(tf32r(sc[n][0]), tf32r(sc[n][1]));
            *(float2*)(sP + (tr + 8) * PS + scol) =
                make_float2(tf32r(sc[n][2]), tf32r(sc[n][3]));
        }
        if (q4 == 0) { sA[tr] = al0; sA[tr + 8] = al1; }
        __syncthreads();

        // ---- rescale O^T cols by alpha[t], then GEMM2: O^T(c x t) += V(c x s) * P^T(s x t)
        #pragma unroll
        for (int n = 0; n < 8; n++) {
            const float av0 = sA[n * 8 + 2 * q4];
            const float av1 = sA[n * 8 + 2 * q4 + 1];
            oc[n][0] *= av0; oc[n][1] *= av1;
            oc[n][2] *= av0; oc[n][3] *= av1;
        }
        uint32_t av[8][4];
        #pragma unroll
        for (int k = 0; k < 8; k++) {
            const int kk = k * 8 + q4;
            av[k][0] = fb(sV[ cr      * VS + kk    ]);
            av[k][1] = fb(sV[(cr + 8) * VS + kk    ]);
            av[k][2] = fb(sV[ cr      * VS + kk + 4]);
            av[k][3] = fb(sV[(cr + 8) * VS + kk + 4]);
        }
        #pragma unroll
        for (int n = 0; n < 8; n++) {
            const int bn = n * 8 + g4;    // t-col group
            #pragma unroll
            for (int k = 0; k < 8; k++) {
                const int br = k * 8 + q4; // s-row
                uint32_t b0 = fb(sP[bn * PS + br    ]);
                uint32_t b1 = fb(sP[bn * PS + br + 4]);
                mma8(oc[n], av[k], b0, b1);
            }
        }
        __syncthreads();   // protect sK/sV/sP/sA before next iteration overwrites
    }

    // ---- finalize: divide columns by l[t], write O^T directly ([c][t] matches global)
    if (q4 == 0) { sLi[tr] = 1.0f / l0; sLi[tr + 8] = 1.0f / l1; }
    __syncthreads();

    #pragma unroll
    for (int n = 0; n < 8; n++) {
        const int tcol = n * 8 + 2 * q4;
        const float li0 = sLi[tcol];
        const float li1 = sLi[tcol + 1];
        float2 w0 = make_float2(oc[n][0] * li0, oc[n][1] * li1);
        float2 w1 = make_float2(oc[n][2] * li0, oc[n][3] * li1);
        *(float2*)(gO + (size_t)cr       * L + t0 + tcol) = w0;
        *(float2*)(gO + (size_t)(cr + 8) * L + t0 + tcol) = w1;
    }
}

} // anonymous namespace

extern "C" void kernel_launch(void* const* d_in, const int* in_sizes, int n_in,
                              void* d_out, int out_size)
{
    const float* qkv = (const float*)d_in[0];
    float* out = (float*)d_out;

    cudaFuncSetAttribute(attn_kernel,
                         cudaFuncAttributeMaxDynamicSharedMemorySize, SMEM_BYTES);

    dim3 grid(L / BT, 32);   // 32 t-tiles x 32 (batch*head)
    attn_kernel<<<grid, NTHREADS, SMEM_BYTES>>>(qkv, out);
}

// round 7
// speedup vs baseline: 1.0455x; 1.0448x over previous
#include <cuda_runtime.h>
#include <cstdint>

namespace {

constexpr int L  = 2048;   // sequence length
constexpr int CH = 64;     // head dim
constexpr int BT = 64;     // query tile per CTA
constexpr int BS = 64;     // kv tile per iteration
constexpr int QS = 68;     // sQ row stride, layout [t][c] (prologue overlay)
constexpr int KS = 72;     // sK row stride, layout [c][s]
constexpr int VS = 68;     // sV row stride, layout [c][s]
constexpr int TS = 72;     // sT row stride, layout [c][t] (epilogue overlay)
constexpr int NTHREADS = 128;

constexpr int SMEM_FLOATS = CH * KS + CH * VS;   // 8960 floats = 35,840 B

__device__ __forceinline__ float tf32r(float x) {
    uint32_t u;
    asm("cvt.rna.tf32.f32 %0, %1;" : "=r"(u) : "f"(x));
    return __uint_as_float(u);
}
__device__ __forceinline__ uint32_t fb(float x) { return __float_as_uint(x); }

// D(16x8) += A(16x8,row) * B(8x8,col), tf32 inputs, f32 accumulate
__device__ __forceinline__ void mma8(float c[4], const uint32_t a[4],
                                     uint32_t b0, uint32_t b1) {
    asm volatile(
        "mma.sync.aligned.m16n8k8.row.col.f32.tf32.tf32.f32 "
        "{%0,%1,%2,%3}, {%4,%5,%6,%7}, {%8,%9}, {%0,%1,%2,%3};"
        : "+f"(c[0]), "+f"(c[1]), "+f"(c[2]), "+f"(c[3])
        : "r"(a[0]), "r"(a[1]), "r"(a[2]), "r"(a[3]), "r"(b0), "r"(b1));
}

__global__ void __launch_bounds__(NTHREADS, 4)
attn_kernel(const float* __restrict__ qkv, float* __restrict__ out)
{
    __shared__ float sm[SMEM_FLOATS];
    float* sK = sm;              // [CH][KS]  c x s
    float* sV = sm + CH * KS;    // [CH][VS]  c x s
    float* sQ = sm;              // prologue overlay: [BT][QS]  t x c
    float* sT = sm;              // epilogue overlay: [CH][TS]  c x t

    const int tid  = threadIdx.x;
    const int lane = tid & 31;
    const int wid  = tid >> 5;
    const int g4   = lane >> 2;   // groupID (0..7)
    const int q4   = lane & 3;    // thread-in-group

    const int t0   = blockIdx.x * BT;
    const int head = blockIdx.y;          // 0..31 == b*8 + h
    const int b    = head >> 3;
    const int h    = head & 7;

    const float* gQ = qkv + (size_t)(b * 1536 +        h * 64) * L;
    const float* gK = qkv + (size_t)(b * 1536 +  512 + h * 64) * L;
    const float* gV = qkv + (size_t)(b * 1536 + 1024 + h * 64) * L;
    float*       gO = out + (size_t)(b * 512  +        h * 64) * L;

    const int tr = wid * 16 + g4;   // this thread's local t-rows: tr, tr+8

    // ---- prologue: stage Q transposed sQ[t][c] (scaled by 1/8, tf32), hoist A-frags
    {
        const int r0 = tid >> 4;            // channel row
        const int c4 = (tid & 15) << 2;     // t offset
        #pragma unroll
        for (int r = r0; r < CH; r += 8) {
            float4 v = *(const float4*)(gQ + (size_t)r * L + t0 + c4);
            sQ[(c4 + 0) * QS + r] = tf32r(v.x * 0.125f);
            sQ[(c4 + 1) * QS + r] = tf32r(v.y * 0.125f);
            sQ[(c4 + 2) * QS + r] = tf32r(v.z * 0.125f);
            sQ[(c4 + 3) * QS + r] = tf32r(v.w * 0.125f);
        }
    }
    __syncthreads();

    uint32_t aq[8][4];
    #pragma unroll
    for (int k = 0; k < 8; k++) {
        const int kc = k * 8 + q4;
        aq[k][0] = fb(sQ[ tr      * QS + kc    ]);
        aq[k][1] = fb(sQ[(tr + 8) * QS + kc    ]);
        aq[k][2] = fb(sQ[ tr      * QS + kc + 4]);
        aq[k][3] = fb(sQ[(tr + 8) * QS + kc + 4]);
    }
    __syncthreads();   // sQ dead; sK/sV staging may overwrite

    // O accumulators: O[t][c] fragments — rows tr/tr+8 (match softmax ownership),
    // n-tile n covers c-cols [8n, 8n+8)
    float oc[8][4];
    #pragma unroll
    for (int n = 0; n < 8; n++) {
        oc[n][0] = 0.f; oc[n][1] = 0.f; oc[n][2] = 0.f; oc[n][3] = 0.f;
    }
    float m0 = -INFINITY, m1 = -INFINITY, l0 = 0.f, l1 = 0.f;

    // shuffle sources for the C-frag -> A-frag permutation (quad-local)
    const int src1 = (lane & 0x1C) | (q4 >> 1);   // owner of col q4   (pair j = q4>>1)
    const int src2 = src1 + 2;                    // owner of col q4+4
    const bool odd = (q4 & 1);

    for (int sb = 0; sb < L; sb += BS) {
        // ---- stage K, V tiles: tf32-round in registers, STS.128 (conflict-free)
        {
            const int r0 = tid >> 4;
            const int c4 = (tid & 15) << 2;
            #pragma unroll
            for (int r = r0; r < CH; r += 8) {
                float4 kv = *(const float4*)(gK + (size_t)r * L + sb + c4);
                float4 kr = make_float4(tf32r(kv.x), tf32r(kv.y), tf32r(kv.z), tf32r(kv.w));
                *(float4*)(sK + r * KS + c4) = kr;
                float4 vv = *(const float4*)(gV + (size_t)r * L + sb + c4);
                float4 vr = make_float4(tf32r(vv.x), tf32r(vv.y), tf32r(vv.z), tf32r(vv.w));
                *(float4*)(sV + r * VS + c4) = vr;
            }
        }
        __syncthreads();

        // ---- GEMM1: S(t x s) = Qt(t x c) * K(c x s); warp's 16 t-rows x 64 s-cols
        float sc[8][4];
        #pragma unroll
        for (int n = 0; n < 8; n++) {
            sc[n][0] = 0.f; sc[n][1] = 0.f; sc[n][2] = 0.f; sc[n][3] = 0.f;
        }
        #pragma unroll
        for (int n = 0; n < 8; n++) {
            const int bn = n * 8 + g4;
            #pragma unroll
            for (int k = 0; k < 8; k++) {
                const int br = k * 8 + q4;
                uint32_t b0 = fb(sK[ br      * KS + bn]);
                uint32_t b1 = fb(sK[(br + 4) * KS + bn]);
                mma8(sc[n], aq[k], b0, b1);
            }
        }

        // ---- online softmax (rows tr, tr+8); everything thread-local
        float mx0 = -INFINITY, mx1 = -INFINITY;
        #pragma unroll
        for (int n = 0; n < 8; n++) {
            mx0 = fmaxf(mx0, fmaxf(sc[n][0], sc[n][1]));
            mx1 = fmaxf(mx1, fmaxf(sc[n][2], sc[n][3]));
        }
        mx0 = fmaxf(mx0, __shfl_xor_sync(0xFFFFFFFFu, mx0, 1));
        mx0 = fmaxf(mx0, __shfl_xor_sync(0xFFFFFFFFu, mx0, 2));
        mx1 = fmaxf(mx1, __shfl_xor_sync(0xFFFFFFFFu, mx1, 1));
        mx1 = fmaxf(mx1, __shfl_xor_sync(0xFFFFFFFFu, mx1, 2));

        const float mn0 = fmaxf(m0, mx0);
        const float mn1 = fmaxf(m1, mx1);
        const float al0 = __expf(m0 - mn0);
        const float al1 = __expf(m1 - mn1);

        float s0 = 0.f, s1 = 0.f;
        #pragma unroll
        for (int n = 0; n < 8; n++) {
            float e0 = __expf(sc[n][0] - mn0);
            float e1 = __expf(sc[n][1] - mn0);
            float e2 = __expf(sc[n][2] - mn1);
            float e3 = __expf(sc[n][3] - mn1);
            s0 += e0 + e1;  s1 += e2 + e3;
            // store tf32-rounded P back into sc (bit image) for the shuffle permute
            sc[n][0] = tf32r(e0); sc[n][1] = tf32r(e1);
            sc[n][2] = tf32r(e2); sc[n][3] = tf32r(e3);
        }
        s0 += __shfl_xor_sync(0xFFFFFFFFu, s0, 1);
        s0 += __shfl_xor_sync(0xFFFFFFFFu, s0, 2);
        s1 += __shfl_xor_sync(0xFFFFFFFFu, s1, 1);
        s1 += __shfl_xor_sync(0xFFFFFFFFu, s1, 2);

        l0 = l0 * al0 + s0;  m0 = mn0;
        l1 = l1 * al1 + s1;  m1 = mn1;

        // ---- rescale O (rows are local!): c0,c1 row tr (*al0); c2,c3 row tr+8 (*al1)
        #pragma unroll
        for (int n = 0; n < 8; n++) {
            oc[n][0] *= al0; oc[n][1] *= al0;
            oc[n][2] *= al1; oc[n][3] *= al1;
        }

        // ---- GEMM2: O[16t x 64c] += P(regs, shuffled to A-frags) * V^T(sV swapped-index)
        #pragma unroll
        for (int k = 0; k < 8; k++) {
            // permute C-frag layout of P k-tile into A-frag layout
            uint32_t u0 = __shfl_sync(0xFFFFFFFFu, fb(sc[k][0]), src1);
            uint32_t u1 = __shfl_sync(0xFFFFFFFFu, fb(sc[k][1]), src1);
            uint32_t u2 = __shfl_sync(0xFFFFFFFFu, fb(sc[k][2]), src1);
            uint32_t u3 = __shfl_sync(0xFFFFFFFFu, fb(sc[k][3]), src1);
            uint32_t v0 = __shfl_sync(0xFFFFFFFFu, fb(sc[k][0]), src2);
            uint32_t v1 = __shfl_sync(0xFFFFFFFFu, fb(sc[k][1]), src2);
            uint32_t v2 = __shfl_sync(0xFFFFFFFFu, fb(sc[k][2]), src2);
            uint32_t v3 = __shfl_sync(0xFFFFFFFFu, fb(sc[k][3]), src2);
            uint32_t ap[4];
            ap[0] = odd ? u1 : u0;   // A[tr  ][8k+q4]
            ap[1] = odd ? u3 : u2;   // A[tr+8][8k+q4]
            ap[2] = odd ? v1 : v0;   // A[tr  ][8k+q4+4]
            ap[3] = odd ? v3 : v2;   // A[tr+8][8k+q4+4]
            const int br0 = 8 * k + q4;
            #pragma unroll
            for (int n = 0; n < 8; n++) {
                const int bn = n * 8 + g4;          // c-col
                uint32_t b0 = fb(sV[bn * VS + br0    ]);   // V^T[s][c] = sV[c][s]
                uint32_t b1 = fb(sV[bn * VS + br0 + 4]);
                mma8(oc[n], ap, b0, b1);
            }
        }
        __syncthreads();   // sK/sV consumed; safe to restage next iteration
    }

    // ---- epilogue: divide rows by l (thread-local), transpose via smem, coalesced store
    const float li0 = 1.0f / l0;
    const float li1 = 1.0f / l1;
    #pragma unroll
    for (int n = 0; n < 8; n++) {
        const int c0 = n * 8 + 2 * q4;
        sT[ c0      * TS + tr    ] = oc[n][0] * li0;
        sT[(c0 + 1) * TS + tr    ] = oc[n][1] * li0;
        sT[ c0      * TS + tr + 8] = oc[n][2] * li1;
        sT[(c0 + 1) * TS + tr + 8] = oc[n][3] * li1;
    }
    __syncthreads();

    #pragma unroll
    for (int i = 0; i < 8; i++) {
        const int lin = tid + NTHREADS * i;    // 0..1023
        const int r   = lin >> 4;              // channel row 0..63
        const int c4  = (lin & 15) << 2;       // t offset
        float4 v = *(const float4*)(sT + r * TS + c4);
        *(float4*)(gO + (size_t)r * L + t0 + c4) = v;
    }
}

} // anonymous namespace

extern "C" void kernel_launch(void* const* d_in, const int* in_sizes, int n_in,
                              void* d_out, int out_size)
{
    const float* qkv = (const float*)d_in[0];
    float* out = (float*)d_out;

    dim3 grid(L / BT, 32);   // 32 t-tiles x 32 (batch*head)
    attn_kernel<<<grid, NTHREADS>>>(qkv, out);
}